// round 10
// baseline (speedup 1.0000x reference)
#include <cuda_runtime.h>
#include <cuda_fp16.h>

// Problem constants
#define DVOL 160
#define HWS  25600            // 160*160
#define VOL  4096000          // 160^3
#define NTOT 8192000          // 2 * 160^3

#define K1_BLOCKS 8000        // 5*5*320
#define K2_BLOCKS 400         // 100*4
#define DSEG 40               // depth segment length in k2

// Packed fp16 intermediates:
//   g01[idx] = half2(blur(p),   blur(t))
//   g23[idx] = half2(blur(p*p), blur(t*t))
//   g4 [idx] = half (blur(p*t))
__device__ __half2 g01[NTOT];
__device__ __half2 g23[NTOT];
__device__ __half  g4[NTOT];
__device__ float g_l1_part[K1_BLOCKS];
__device__ float g_ssim_part[K2_BLOCKS];

// Gaussian weights (size 11, sigma 1.5, normalized). Symmetric: w[j]=w[10-j].
#define GW_INIT {0.00102838f, 0.00759876f, 0.03600078f, 0.10936070f, \
                 0.21300554f, 0.26601172f, 0.21300554f, 0.10936070f, \
                 0.03600078f, 0.00759876f, 0.00102838f}
// distinct values only (j=0..5)
#define GWS_INIT {0.00102838f, 0.00759876f, 0.03600078f, 0.10936070f, \
                  0.21300554f, 0.26601172f}
#define JSYM(j) ((j) <= 5 ? (j) : 10 - (j))

// ---- packed f32x2 helpers (Blackwell FFMA2 path, PTX-only) ---------------
typedef unsigned long long u64;

__device__ __forceinline__ u64 ffma2(u64 a, u64 b, u64 c) {
    u64 r;
    asm("fma.rn.f32x2 %0, %1, %2, %3;" : "=l"(r) : "l"(a), "l"(b), "l"(c));
    return r;
}
__device__ __forceinline__ u64 fmul2(u64 a, u64 b) {
    u64 r;
    asm("mul.rn.f32x2 %0, %1, %2;" : "=l"(r) : "l"(a), "l"(b));
    return r;
}
__device__ __forceinline__ u64 pack2(float lo, float hi) {
    u64 r;
    asm("mov.b64 %0, {%1, %2};"
        : "=l"(r) : "r"(__float_as_uint(lo)), "r"(__float_as_uint(hi)));
    return r;
}
__device__ __forceinline__ float2 unpack2(u64 v) {
    unsigned lo, hi;
    asm("mov.b64 {%0, %1}, %2;" : "=r"(lo), "=r"(hi) : "l"(v));
    return make_float2(__uint_as_float(lo), __uint_as_float(hi));
}

// ---------------------------------------------------------------------------
// Kernel 1: per (n,d) slice, fused W-blur + H-blur of the 5 product channels,
// 32x32 output tiles, f32x2-packed math, packed fp16 outputs + L1 partial.
// ---------------------------------------------------------------------------
__global__ __launch_bounds__(256, 5) void k_blur_wh(
    const float* __restrict__ pred, const float* __restrict__ tgt)
{
    __shared__ u64 rpt[42][45];           // raw (p,t) packed; 8B-stride 45 mod 16 = 13
    __shared__ u64 stP[2][42][33];        // W-blurred pairs (p,t), (pp,tt)
    __shared__ float stS[42][33];         // W-blurred pt
    __shared__ float red[8];

    const float GWS[6] = GWS_INIT;
    u64 w2s[6];
#pragma unroll
    for (int j = 0; j < 6; j++) w2s[j] = pack2(GWS[j], GWS[j]);

    const int bz = blockIdx.z;            // n*160 + d
    const int n  = bz / DVOL;
    const int d  = bz % DVOL;
    const int h0 = blockIdx.y * 32;
    const int w0 = blockIdx.x * 32;
    const int base = n * VOL + d * HWS;
    const int tid = threadIdx.x;

    // --- load raw 42x42 halo region (zero padded), incremental indexing ---
    {
        int r = tid / 42;
        int c = tid - r * 42;
        while (r < 42) {
            const int gh = h0 - 5 + r;
            const int gw = w0 - 5 + c;
            float p = 0.f, t = 0.f;
            if ((unsigned)gh < 160u && (unsigned)gw < 160u) {
                const int idx = base + gh * DVOL + gw;
                p = pred[idx];
                t = tgt[idx];
            }
            rpt[r][c] = pack2(p, t);
            r += 6; c += 4;                  // advance by 256 = 6*42 + 4
            if (c >= 42) { c -= 42; r += 1; }
        }
    }
    __syncthreads();

    // --- L1 partial over the 32x32 interior -------------------------------
    float l1 = 0.f;
#pragma unroll
    for (int k = 0; k < 4; k++) {
        const int i = tid + (k << 8);
        const int hh = i >> 5, ww = i & 31;
        const float2 v = unpack2(rpt[5 + hh][5 + ww]);
        l1 += fabsf(v.x - v.y);
    }

    // --- phase A: blur along W, packed ring (no pt ring: computed per tap) -
    // thread = (row r in 0..41, col-group g in 0..5), each group covers 6 cols
    if (tid < 252) {
        const int g = tid / 42;
        const int r = tid - 42 * g;
        const int c0 = g * 6;

        u64 q01[11];
#pragma unroll
        for (int k = 0; k < 10; k++) q01[k] = rpt[r][c0 + k];

#pragma unroll
        for (int s = 0; s < 6; s++) {
            const int c = c0 + s;
            if (c < 32) {
                const int sl = (s + 10) % 11;
                q01[sl] = rpt[r][c + 10];
                u64 a01 = 0ull, a23 = 0ull;
                float a4 = 0.f;
#pragma unroll
                for (int j = 0; j < 11; j++) {
                    const int q = (s + j) % 11;
                    const u64 x = q01[q];
                    const u64 w = w2s[JSYM(j)];
                    a01 = ffma2(x, w, a01);
                    a23 = ffma2(fmul2(x, x), w, a23);
                    const float2 f = unpack2(x);     // free (register halves)
                    a4 += GWS[JSYM(j)] * (f.x * f.y);
                }
                stP[0][r][c] = a01;
                stP[1][r][c] = a23;
                stS[r][c] = a4;
            }
        }
    }

    // reduce L1 (warp shuffles, then smem) — overlaps with phase A compute
#pragma unroll
    for (int o = 16; o; o >>= 1) l1 += __shfl_down_sync(0xffffffffu, l1, o);
    if ((tid & 31) == 0) red[tid >> 5] = l1;

    __syncthreads();   // stP/stS ready + red ready

    if (tid == 0) {
        float s = 0.f;
#pragma unroll
        for (int k = 0; k < 8; k++) s += red[k];
        const int bidlin = blockIdx.x + 5 * (blockIdx.y + 5 * blockIdx.z);
        g_l1_part[bidlin] = s;
    }

    // --- phase B pass 1: packed pairs on ALL 256 threads -------------------
    // thread = (channel ch in 0..1, hgroup hg in 0..3 of 8 rows, col ww)
    {
        const int ch  = tid >> 7;            // 0 or 1
        const int sub = tid & 127;
        const int hg  = sub >> 5;            // 0..3
        const int ww  = sub & 31;
        const int rbase = hg * 8;

        u64 acc[8];
#pragma unroll
        for (int o = 0; o < 8; o++) acc[o] = 0ull;
#pragma unroll
        for (int rr = 0; rr < 18; rr++) {
            const u64 v = stP[ch][rbase + rr][ww];
#pragma unroll
            for (int o = 0; o < 8; o++) {
                const int j = rr - o;                 // compile-time bounds
                if (j >= 0 && j <= 10)
                    acc[o] = ffma2(v, w2s[JSYM(j)], acc[o]);
            }
        }
        __half2* __restrict__ out = ch ? g23 : g01;
        const int obase = base + (h0 + rbase) * DVOL + w0 + ww;
#pragma unroll
        for (int o = 0; o < 8; o++) {
            const float2 f = unpack2(acc[o]);
            out[obase + o * DVOL] = __floats2half2_rn(f.x, f.y);
        }
    }

    // --- phase B pass 2: scalar pt channel on 128 threads ------------------
    if (tid < 128) {
        const int hg = tid >> 5;
        const int ww = tid & 31;
        const int rbase = hg * 8;

        float acc[8];
#pragma unroll
        for (int o = 0; o < 8; o++) acc[o] = 0.f;
#pragma unroll
        for (int rr = 0; rr < 18; rr++) {
            const float v = stS[rbase + rr][ww];
#pragma unroll
            for (int o = 0; o < 8; o++) {
                const int j = rr - o;
                if (j >= 0 && j <= 10) acc[o] += GWS[JSYM(j)] * v;
            }
        }
        const int obase = base + (h0 + rbase) * DVOL + w0 + ww;
#pragma unroll
        for (int o = 0; o < 8; o++)
            g4[obase + o * DVOL] = __float2half_rn(acc[o]);
    }
}

// ---------------------------------------------------------------------------
// Kernel 2: blur along D, 2 adjacent columns per thread (uint2 loads, 2x MLP),
// half2 rings + HFMA2, SSIM map, per-block reduction. grid: (100, 4).
// ---------------------------------------------------------------------------
__global__ __launch_bounds__(256) void k_blur_d_ssim()
{
    __half2 gw2s[6];
    const float GWS[6] = GWS_INIT;
#pragma unroll
    for (int j = 0; j < 6; j++) gw2s[j] = __float2half2_rn(GWS[j]);

    const int pairidx = blockIdx.x * 256 + threadIdx.x;   // 0..25599
    const int n  = pairidx / (HWS / 2);
    const int hw = (pairidx - n * (HWS / 2)) * 2;
    const int dstart = blockIdx.y * DSEG;
    const int base = n * VOL + hw;

    uint2 r01[11], r23[11];
    unsigned r4[11];
#pragma unroll
    for (int k = 0; k < 11; k++) {
        r01[k] = make_uint2(0u, 0u);
        r23[k] = make_uint2(0u, 0u);
        r4[k] = 0u;
    }

    // preload depths dstart-5 .. dstart+4 into slots 0..9
#pragma unroll
    for (int k = 0; k < 10; k++) {
        const int dep = dstart - 5 + k;
        if (dep >= 0) {
            const int idx = base + dep * HWS;
            r01[k] = *(const uint2*)(g01 + idx);
            r23[k] = *(const uint2*)(g23 + idx);
            r4[k]  = *(const unsigned*)(g4 + idx);
        }
    }

    const __half2 hz = __float2half2_rn(0.f);
    float ssim_acc = 0.f;
    for (int s0 = 0; s0 < 44; s0 += 11) {
#pragma unroll
        for (int u = 0; u < 11; u++) {
            const int s = s0 + u;
            if (s < DSEG) {
                const int dep = dstart + s + 5;
                const int sl = (u + 10) % 11;
                if (dep < DVOL) {
                    const int idx = base + dep * HWS;
                    r01[sl] = *(const uint2*)(g01 + idx);
                    r23[sl] = *(const uint2*)(g23 + idx);
                    r4[sl]  = *(const unsigned*)(g4 + idx);
                } else {
                    r01[sl] = make_uint2(0u, 0u);
                    r23[sl] = make_uint2(0u, 0u);
                    r4[sl] = 0u;
                }
                __half2 mA = hz, mB = hz, eA = hz, eB = hz, e4 = hz;
#pragma unroll
                for (int j = 0; j < 11; j++) {
                    const int q = (u + j) % 11;
                    const __half2 w = gw2s[JSYM(j)];
                    mA = __hfma2(w, *(const __half2*)&r01[q].x, mA);
                    mB = __hfma2(w, *(const __half2*)&r01[q].y, mB);
                    eA = __hfma2(w, *(const __half2*)&r23[q].x, eA);
                    eB = __hfma2(w, *(const __half2*)&r23[q].y, eB);
                    e4 = __hfma2(w, *(const __half2*)&r4[q],   e4);
                }
                const float2 e4f = __half22float2(e4);
#pragma unroll
                for (int cc = 0; cc < 2; cc++) {
                    const float2 mu = __half22float2(cc ? mB : mA);
                    const float2 ev = __half22float2(cc ? eB : eA);
                    const float e12 = cc ? e4f.y : e4f.x;
                    const float mu1sq = mu.x * mu.x;
                    const float mu2sq = mu.y * mu.y;
                    const float mu12  = mu.x * mu.y;
                    const float s1  = ev.x - mu1sq;
                    const float s2  = ev.y - mu2sq;
                    const float s12 = e12 - mu12;
                    const float C1 = 1e-4f, C2 = 9e-4f;
                    const float num = (2.f * mu12 + C1) * (2.f * s12 + C2);
                    const float den = (mu1sq + mu2sq + C1) * (s1 + s2 + C2) + 1e-12f;
                    ssim_acc += __fdividef(num, den);
                }
            }
        }
    }

    // block reduction
    __shared__ float red[8];
#pragma unroll
    for (int o = 16; o; o >>= 1)
        ssim_acc += __shfl_down_sync(0xffffffffu, ssim_acc, o);
    if ((threadIdx.x & 31) == 0) red[threadIdx.x >> 5] = ssim_acc;
    __syncthreads();
    if (threadIdx.x == 0) {
        float s = 0.f;
#pragma unroll
        for (int k = 0; k < 8; k++) s += red[k];
        g_ssim_part[blockIdx.x + 100 * blockIdx.y] = s;
    }
}

// ---------------------------------------------------------------------------
// Final: reduce the partial arrays (8000 + 400 floats) and combine.
// ---------------------------------------------------------------------------
__global__ __launch_bounds__(256) void k_final(float* __restrict__ out) {
    const int tid = threadIdx.x;
    double l1 = 0.0, ss = 0.0;
    for (int i = tid; i < K1_BLOCKS; i += 256) l1 += (double)g_l1_part[i];
    for (int i = tid; i < K2_BLOCKS; i += 256) ss += (double)g_ssim_part[i];

    __shared__ double rl[8], rs[8];
#pragma unroll
    for (int o = 16; o; o >>= 1) {
        l1 += __shfl_down_sync(0xffffffffu, l1, o);
        ss += __shfl_down_sync(0xffffffffu, ss, o);
    }
    if ((tid & 31) == 0) { rl[tid >> 5] = l1; rs[tid >> 5] = ss; }
    __syncthreads();
    if (tid == 0) {
        double a = 0.0, b = 0.0;
#pragma unroll
        for (int k = 0; k < 8; k++) { a += rl[k]; b += rs[k]; }
        const double inv = 1.0 / (double)NTOT;
        out[0] = (float)(0.7 * (a * inv) + 0.3 * (1.0 - b * inv));
    }
}

extern "C" void kernel_launch(void* const* d_in, const int* in_sizes, int n_in,
                              void* d_out, int out_size)
{
    const float* pred = (const float*)d_in[0];
    const float* tgt  = (const float*)d_in[1];
    float* out = (float*)d_out;

    dim3 g1(5, 5, 2 * DVOL);          // w-tiles, h-tiles, n*d
    k_blur_wh<<<g1, 256>>>(pred, tgt);

    dim3 g2(100, 4);                  // column pairs, depth segments
    k_blur_d_ssim<<<g2, 256>>>();

    k_final<<<1, 256>>>(out);
}

// round 11
// speedup vs baseline: 1.7515x; 1.7515x over previous
#include <cuda_runtime.h>
#include <cuda_fp16.h>

// Problem constants
#define DVOL 160
#define HWS  25600            // 160*160
#define VOL  4096000          // 160^3
#define NTOT 8192000          // 2 * 160^3

#define K1_BLOCKS 8000        // 5*5*320
#define K2_BLOCKS 1600        // 200*8
#define DSEG 20               // depth segment length in k2

// Packed fp16 intermediates:
//   g01[idx] = half2(blur(p),   blur(t))
//   g23[idx] = half2(blur(p*p), blur(t*t))
//   g4 [idx] = half (blur(p*t))
__device__ __half2 g01[NTOT];
__device__ __half2 g23[NTOT];
__device__ __half  g4[NTOT];
__device__ float g_l1_part[K1_BLOCKS];
__device__ float g_ssim_part[K2_BLOCKS];

// Gaussian weights (size 11, sigma 1.5, normalized).
#define GW_INIT {0.00102838f, 0.00759876f, 0.03600078f, 0.10936070f, \
                 0.21300554f, 0.26601172f, 0.21300554f, 0.10936070f, \
                 0.03600078f, 0.00759876f, 0.00102838f}

// ---- packed f32x2 helpers (Blackwell FFMA2 path, PTX-only) ---------------
typedef unsigned long long u64;

__device__ __forceinline__ u64 ffma2(u64 a, u64 b, u64 c) {
    u64 r;
    asm("fma.rn.f32x2 %0, %1, %2, %3;" : "=l"(r) : "l"(a), "l"(b), "l"(c));
    return r;
}
__device__ __forceinline__ u64 fmul2(u64 a, u64 b) {
    u64 r;
    asm("mul.rn.f32x2 %0, %1, %2;" : "=l"(r) : "l"(a), "l"(b));
    return r;
}
__device__ __forceinline__ u64 pack2(float lo, float hi) {
    u64 r;
    asm("mov.b64 %0, {%1, %2};"
        : "=l"(r) : "r"(__float_as_uint(lo)), "r"(__float_as_uint(hi)));
    return r;
}
__device__ __forceinline__ float2 unpack2(u64 v) {
    unsigned lo, hi;
    asm("mov.b64 {%0, %1}, %2;" : "=r"(lo), "=r"(hi) : "l"(v));
    return make_float2(__uint_as_float(lo), __uint_as_float(hi));
}

// ---------------------------------------------------------------------------
// Kernel 1 (R9-proven, 77.3us): per (n,d) slice, fused W-blur + H-blur of the
// 5 product channels, 32x32 tiles, f32x2 math, packed fp16 out + L1 partial.
// NOTE: no min-blocks launch bound — phase A needs its 62 registers.
// ---------------------------------------------------------------------------
__global__ __launch_bounds__(256) void k_blur_wh(
    const float* __restrict__ pred, const float* __restrict__ tgt)
{
    __shared__ u64 rpt[42][45];           // raw (p,t) packed; 8B-stride 45 mod 16 = 13
    __shared__ u64 stP[2][42][33];        // W-blurred pairs (p,t), (pp,tt)
    __shared__ float stS[42][33];         // W-blurred pt
    __shared__ float red[8];

    const float GW[11] = GW_INIT;
    u64 w2[11];
#pragma unroll
    for (int j = 0; j < 11; j++) w2[j] = pack2(GW[j], GW[j]);

    const int bz = blockIdx.z;            // n*160 + d
    const int n  = bz / DVOL;
    const int d  = bz % DVOL;
    const int h0 = blockIdx.y * 32;
    const int w0 = blockIdx.x * 32;
    const int base = n * VOL + d * HWS;
    const int tid = threadIdx.x;

    // --- load raw 42x42 halo region (zero padded), incremental indexing ---
    {
        int r = tid / 42;
        int c = tid - r * 42;
        while (r < 42) {
            const int gh = h0 - 5 + r;
            const int gw = w0 - 5 + c;
            float p = 0.f, t = 0.f;
            if ((unsigned)gh < 160u && (unsigned)gw < 160u) {
                const int idx = base + gh * DVOL + gw;
                p = pred[idx];
                t = tgt[idx];
            }
            rpt[r][c] = pack2(p, t);
            r += 6; c += 4;                  // advance by 256 = 6*42 + 4
            if (c >= 42) { c -= 42; r += 1; }
        }
    }
    __syncthreads();

    // --- L1 partial over the 32x32 interior -------------------------------
    float l1 = 0.f;
#pragma unroll
    for (int k = 0; k < 4; k++) {
        const int i = tid + (k << 8);
        const int hh = i >> 5, ww = i & 31;
        const float2 v = unpack2(rpt[5 + hh][5 + ww]);
        l1 += fabsf(v.x - v.y);
    }

    // --- phase A: blur along W, packed rings -------------------------------
    // thread = (row r in 0..41, col-group g in 0..5), each group covers 6 cols
    if (tid < 252) {
        const int g = tid / 42;
        const int r = tid - 42 * g;
        const int c0 = g * 6;

        u64 q01[11];
        float q4[11];
#pragma unroll
        for (int k = 0; k < 10; k++) {
            const u64 v = rpt[r][c0 + k];
            q01[k] = v;
            const float2 f = unpack2(v);
            q4[k] = f.x * f.y;
        }
#pragma unroll
        for (int s = 0; s < 6; s++) {
            const int c = c0 + s;
            if (c < 32) {
                const u64 v = rpt[r][c + 10];
                const int sl = (s + 10) % 11;
                q01[sl] = v;
                {
                    const float2 f = unpack2(v);
                    q4[sl] = f.x * f.y;
                }
                u64 a01 = 0ull, a23 = 0ull;
                float a4 = 0.f;
#pragma unroll
                for (int j = 0; j < 11; j++) {
                    const int q = (s + j) % 11;
                    const u64 x = q01[q];
                    a01 = ffma2(x, w2[j], a01);
                    a23 = ffma2(fmul2(x, x), w2[j], a23);
                    a4 += GW[j] * q4[q];
                }
                stP[0][r][c] = a01;
                stP[1][r][c] = a23;
                stS[r][c] = a4;
            }
        }
    }

    // reduce L1 (warp shuffles, then smem) — overlaps with phase A compute
#pragma unroll
    for (int o = 16; o; o >>= 1) l1 += __shfl_down_sync(0xffffffffu, l1, o);
    if ((tid & 31) == 0) red[tid >> 5] = l1;

    __syncthreads();   // stP/stS ready + red ready

    if (tid == 0) {
        float s = 0.f;
#pragma unroll
        for (int k = 0; k < 8; k++) s += red[k];
        const int bidlin = blockIdx.x + 5 * (blockIdx.y + 5 * blockIdx.z);
        g_l1_part[bidlin] = s;
    }

    // --- phase B pass 1: packed pairs on ALL 256 threads -------------------
    // thread = (channel ch in 0..1, hgroup hg in 0..3 of 8 rows, col ww)
    {
        const int ch  = tid >> 7;            // 0 or 1
        const int sub = tid & 127;
        const int hg  = sub >> 5;            // 0..3
        const int ww  = sub & 31;
        const int rbase = hg * 8;

        u64 acc[8];
#pragma unroll
        for (int o = 0; o < 8; o++) acc[o] = 0ull;
#pragma unroll
        for (int rr = 0; rr < 18; rr++) {
            const u64 v = stP[ch][rbase + rr][ww];
#pragma unroll
            for (int o = 0; o < 8; o++) {
                const int j = rr - o;                 // compile-time bounds
                if (j >= 0 && j <= 10) acc[o] = ffma2(v, w2[j], acc[o]);
            }
        }
        __half2* __restrict__ out = ch ? g23 : g01;
        const int obase = base + (h0 + rbase) * DVOL + w0 + ww;
#pragma unroll
        for (int o = 0; o < 8; o++) {
            const float2 f = unpack2(acc[o]);
            out[obase + o * DVOL] = __floats2half2_rn(f.x, f.y);
        }
    }

    // --- phase B pass 2: scalar pt channel on 128 threads ------------------
    if (tid < 128) {
        const int hg = tid >> 5;
        const int ww = tid & 31;
        const int rbase = hg * 8;

        float acc[8];
#pragma unroll
        for (int o = 0; o < 8; o++) acc[o] = 0.f;
#pragma unroll
        for (int rr = 0; rr < 18; rr++) {
            const float v = stS[rbase + rr][ww];
#pragma unroll
            for (int o = 0; o < 8; o++) {
                const int j = rr - o;
                if (j >= 0 && j <= 10) acc[o] += GW[j] * v;
            }
        }
        const int obase = base + (h0 + rbase) * DVOL + w0 + ww;
#pragma unroll
        for (int o = 0; o < 8; o++)
            g4[obase + o * DVOL] = __float2half_rn(acc[o]);
    }
}

// ---------------------------------------------------------------------------
// Kernel 2 (R6-proven, ~43.6us): blur along D, ONE column per thread (low
// register pressure -> 4 blocks/SM), half2 rings + HFMA2, SSIM map,
// per-block reduction. grid: (200, 8) — 8 depth segments of 20.
// ---------------------------------------------------------------------------
__global__ __launch_bounds__(256) void k_blur_d_ssim()
{
    __half2 gw2[11];
    {
        const float GW[11] = GW_INIT;
#pragma unroll
        for (int j = 0; j < 11; j++) gw2[j] = __float2half2_rn(GW[j]);
    }

    const int col = blockIdx.x * 256 + threadIdx.x;   // 0..51199
    const int n  = col / HWS;
    const int hw = col - n * HWS;
    const int dstart = blockIdx.y * DSEG;
    const int base = n * VOL + hw;

    const __half2 hz = __float2half2_rn(0.f);
    __half2 r01[11], r23[11];
    float r4[11];
#pragma unroll
    for (int k = 0; k < 11; k++) { r01[k] = hz; r23[k] = hz; r4[k] = 0.f; }

    // preload depths dstart-5 .. dstart+4 into slots 0..9
#pragma unroll
    for (int k = 0; k < 10; k++) {
        const int dep = dstart - 5 + k;
        if (dep >= 0) {
            const int idx = base + dep * HWS;
            r01[k] = g01[idx];
            r23[k] = g23[idx];
            r4[k]  = __half2float(g4[idx]);
        }
    }

    float ssim_acc = 0.f;
    for (int s0 = 0; s0 < 22; s0 += 11) {
#pragma unroll
        for (int u = 0; u < 11; u++) {
            const int s = s0 + u;
            if (s < DSEG) {
                const int dep = dstart + s + 5;
                const int sl = (u + 10) % 11;
                if (dep < DVOL) {
                    const int idx = base + dep * HWS;
                    r01[sl] = g01[idx];
                    r23[sl] = g23[idx];
                    r4[sl]  = __half2float(g4[idx]);
                } else {
                    r01[sl] = hz; r23[sl] = hz; r4[sl] = 0.f;
                }
                __half2 m = hz, e = hz;
                float e12 = 0.f;
                const float GW[11] = GW_INIT;
#pragma unroll
                for (int j = 0; j < 11; j++) {
                    const int q = (u + j) % 11;
                    m = __hfma2(gw2[j], r01[q], m);
                    e = __hfma2(gw2[j], r23[q], e);
                    e12 += GW[j] * r4[q];
                }
                const float2 mu = __half22float2(m);
                const float2 ev = __half22float2(e);
                const float mu1sq = mu.x * mu.x;
                const float mu2sq = mu.y * mu.y;
                const float mu12  = mu.x * mu.y;
                const float s1  = ev.x - mu1sq;
                const float s2  = ev.y - mu2sq;
                const float s12 = e12 - mu12;
                const float C1 = 1e-4f, C2 = 9e-4f;
                const float num = (2.f * mu12 + C1) * (2.f * s12 + C2);
                const float den = (mu1sq + mu2sq + C1) * (s1 + s2 + C2) + 1e-12f;
                ssim_acc += __fdividef(num, den);
            }
        }
    }

    // block reduction
    __shared__ float red[8];
#pragma unroll
    for (int o = 16; o; o >>= 1)
        ssim_acc += __shfl_down_sync(0xffffffffu, ssim_acc, o);
    if ((threadIdx.x & 31) == 0) red[threadIdx.x >> 5] = ssim_acc;
    __syncthreads();
    if (threadIdx.x == 0) {
        float s = 0.f;
#pragma unroll
        for (int k = 0; k < 8; k++) s += red[k];
        g_ssim_part[blockIdx.x + 200 * blockIdx.y] = s;
    }
}

// ---------------------------------------------------------------------------
// Final: reduce the partial arrays (8000 + 1600 floats) and combine.
// ---------------------------------------------------------------------------
__global__ __launch_bounds__(256) void k_final(float* __restrict__ out) {
    const int tid = threadIdx.x;
    double l1 = 0.0, ss = 0.0;
    for (int i = tid; i < K1_BLOCKS; i += 256) l1 += (double)g_l1_part[i];
    for (int i = tid; i < K2_BLOCKS; i += 256) ss += (double)g_ssim_part[i];

    __shared__ double rl[8], rs[8];
#pragma unroll
    for (int o = 16; o; o >>= 1) {
        l1 += __shfl_down_sync(0xffffffffu, l1, o);
        ss += __shfl_down_sync(0xffffffffu, ss, o);
    }
    if ((tid & 31) == 0) { rl[tid >> 5] = l1; rs[tid >> 5] = ss; }
    __syncthreads();
    if (tid == 0) {
        double a = 0.0, b = 0.0;
#pragma unroll
        for (int k = 0; k < 8; k++) { a += rl[k]; b += rs[k]; }
        const double inv = 1.0 / (double)NTOT;
        out[0] = (float)(0.7 * (a * inv) + 0.3 * (1.0 - b * inv));
    }
}

extern "C" void kernel_launch(void* const* d_in, const int* in_sizes, int n_in,
                              void* d_out, int out_size)
{
    const float* pred = (const float*)d_in[0];
    const float* tgt  = (const float*)d_in[1];
    float* out = (float*)d_out;

    dim3 g1(5, 5, 2 * DVOL);          // w-tiles, h-tiles, n*d
    k_blur_wh<<<g1, 256>>>(pred, tgt);

    dim3 g2((2 * HWS) / 256, 8);      // 200 x 8
    k_blur_d_ssim<<<g2, 256>>>();

    k_final<<<1, 256>>>(out);
}

// round 12
// speedup vs baseline: 1.8447x; 1.0532x over previous
#include <cuda_runtime.h>
#include <cuda_fp16.h>

// Problem constants
#define DVOL 160
#define HWS  25600            // 160*160
#define VOL  4096000          // 160^3
#define NTOT 8192000          // 2 * 160^3

#define K1_BLOCKS 8000        // 5*5*320
#define K2_BLOCKS 1600        // 200*8
#define DSEG 20               // depth segment length in k2

// Packed fp16 intermediates:
//   g01[idx] = half2(blur(p),   blur(t))
//   g23[idx] = half2(blur(p*p), blur(t*t))
//   g4 [idx] = half (blur(p*t))
__device__ __half2 g01[NTOT];
__device__ __half2 g23[NTOT];
__device__ __half  g4[NTOT];
__device__ float g_l1_part[K1_BLOCKS];
__device__ float g_ssim_part[K2_BLOCKS];

// Gaussian weights (size 11, sigma 1.5, normalized).
#define GW_INIT {0.00102838f, 0.00759876f, 0.03600078f, 0.10936070f, \
                 0.21300554f, 0.26601172f, 0.21300554f, 0.10936070f, \
                 0.03600078f, 0.00759876f, 0.00102838f}

// ---- packed f32x2 helpers (Blackwell FFMA2 path, PTX-only) ---------------
typedef unsigned long long u64;

__device__ __forceinline__ u64 ffma2(u64 a, u64 b, u64 c) {
    u64 r;
    asm("fma.rn.f32x2 %0, %1, %2, %3;" : "=l"(r) : "l"(a), "l"(b), "l"(c));
    return r;
}
__device__ __forceinline__ u64 fmul2(u64 a, u64 b) {
    u64 r;
    asm("mul.rn.f32x2 %0, %1, %2;" : "=l"(r) : "l"(a), "l"(b));
    return r;
}
__device__ __forceinline__ u64 pack2(float lo, float hi) {
    u64 r;
    asm("mov.b64 %0, {%1, %2};"
        : "=l"(r) : "r"(__float_as_uint(lo)), "r"(__float_as_uint(hi)));
    return r;
}
__device__ __forceinline__ float2 unpack2(u64 v) {
    unsigned lo, hi;
    asm("mov.b64 {%0, %1}, %2;" : "=r"(lo), "=r"(hi) : "l"(v));
    return make_float2(__uint_as_float(lo), __uint_as_float(hi));
}

// ---------------------------------------------------------------------------
// Kernel 1: per (n,d) slice, fused W-blur + H-blur of the 5 product channels,
// 32x32 tiles, f32x2 math, packed fp16 out + L1 partial.
// NOTE: no min-blocks launch bound — phase A needs its 62 registers.
// ---------------------------------------------------------------------------
__global__ __launch_bounds__(256) void k_blur_wh(
    const float* __restrict__ pred, const float* __restrict__ tgt)
{
    __shared__ u64 rpt[42][45];           // raw (p,t) packed; 8B-stride 45 mod 16 = 13
    __shared__ u64 stP[2][42][33];        // W-blurred pairs (p,t), (pp,tt)
    __shared__ float stS[42][34];         // W-blurred pt (pitch 34: LDS.64 aligned)
    __shared__ float red[8];

    const float GW[11] = GW_INIT;
    u64 w2[11];
#pragma unroll
    for (int j = 0; j < 11; j++) w2[j] = pack2(GW[j], GW[j]);

    const int bz = blockIdx.z;            // n*160 + d
    const int n  = bz / DVOL;
    const int d  = bz % DVOL;
    const int h0 = blockIdx.y * 32;
    const int w0 = blockIdx.x * 32;
    const int base = n * VOL + d * HWS;
    const int tid = threadIdx.x;

    // --- load raw 42x42 halo region (zero padded), incremental indexing ---
    {
        int r = tid / 42;
        int c = tid - r * 42;
        while (r < 42) {
            const int gh = h0 - 5 + r;
            const int gw = w0 - 5 + c;
            float p = 0.f, t = 0.f;
            if ((unsigned)gh < 160u && (unsigned)gw < 160u) {
                const int idx = base + gh * DVOL + gw;
                p = pred[idx];
                t = tgt[idx];
            }
            rpt[r][c] = pack2(p, t);
            r += 6; c += 4;                  // advance by 256 = 6*42 + 4
            if (c >= 42) { c -= 42; r += 1; }
        }
    }
    __syncthreads();

    // --- L1 partial over the 32x32 interior -------------------------------
    float l1 = 0.f;
#pragma unroll
    for (int k = 0; k < 4; k++) {
        const int i = tid + (k << 8);
        const int hh = i >> 5, ww = i & 31;
        const float2 v = unpack2(rpt[5 + hh][5 + ww]);
        l1 += fabsf(v.x - v.y);
    }

    // --- phase A: blur along W, packed rings -------------------------------
    // thread = (row r in 0..41, col-group g in 0..5), each group covers 6 cols
    if (tid < 252) {
        const int g = tid / 42;
        const int r = tid - 42 * g;
        const int c0 = g * 6;

        u64 q01[11];
        float q4[11];
#pragma unroll
        for (int k = 0; k < 10; k++) {
            const u64 v = rpt[r][c0 + k];
            q01[k] = v;
            const float2 f = unpack2(v);
            q4[k] = f.x * f.y;
        }
#pragma unroll
        for (int s = 0; s < 6; s++) {
            const int c = c0 + s;
            if (c < 32) {
                const u64 v = rpt[r][c + 10];
                const int sl = (s + 10) % 11;
                q01[sl] = v;
                {
                    const float2 f = unpack2(v);
                    q4[sl] = f.x * f.y;
                }
                u64 a01 = 0ull, a23 = 0ull;
                float a4 = 0.f;
#pragma unroll
                for (int j = 0; j < 11; j++) {
                    const int q = (s + j) % 11;
                    const u64 x = q01[q];
                    a01 = ffma2(x, w2[j], a01);
                    a23 = ffma2(fmul2(x, x), w2[j], a23);
                    a4 += GW[j] * q4[q];
                }
                stP[0][r][c] = a01;
                stP[1][r][c] = a23;
                stS[r][c] = a4;
            }
        }
    }

    // reduce L1 (warp shuffles, then smem) — overlaps with phase A compute
#pragma unroll
    for (int o = 16; o; o >>= 1) l1 += __shfl_down_sync(0xffffffffu, l1, o);
    if ((tid & 31) == 0) red[tid >> 5] = l1;

    __syncthreads();   // stP/stS ready + red ready

    if (tid == 0) {
        float s = 0.f;
#pragma unroll
        for (int k = 0; k < 8; k++) s += red[k];
        const int bidlin = blockIdx.x + 5 * (blockIdx.y + 5 * blockIdx.z);
        g_l1_part[bidlin] = s;
    }

    // --- phase B pass 1: packed pairs on ALL 256 threads -------------------
    // thread = (channel ch in 0..1, hgroup hg in 0..3 of 8 rows, col ww)
    {
        const int ch  = tid >> 7;            // 0 or 1
        const int sub = tid & 127;
        const int hg  = sub >> 5;            // 0..3
        const int ww  = sub & 31;
        const int rbase = hg * 8;

        u64 acc[8];
#pragma unroll
        for (int o = 0; o < 8; o++) acc[o] = 0ull;
#pragma unroll
        for (int rr = 0; rr < 18; rr++) {
            const u64 v = stP[ch][rbase + rr][ww];
#pragma unroll
            for (int o = 0; o < 8; o++) {
                const int j = rr - o;                 // compile-time bounds
                if (j >= 0 && j <= 10) acc[o] = ffma2(v, w2[j], acc[o]);
            }
        }
        __half2* __restrict__ out = ch ? g23 : g01;
        const int obase = base + (h0 + rbase) * DVOL + w0 + ww;
#pragma unroll
        for (int o = 0; o < 8; o++) {
            const float2 f = unpack2(acc[o]);
            out[obase + o * DVOL] = __floats2half2_rn(f.x, f.y);
        }
    }

    // --- phase B pass 2: pt channel, column-paired f32x2 on 256 threads ----
    // thread = (hgroup hg in 0..15 of 2 rows, colpair cp in 0..15)
    {
        const int hg = tid >> 4;             // 0..15
        const int cp = tid & 15;             // 0..15
        const int rbase = hg * 2;

        u64 acc[2];
        acc[0] = 0ull; acc[1] = 0ull;
#pragma unroll
        for (int rr = 0; rr < 12; rr++) {
            // LDS.64 of two adjacent columns (pitch 34 keeps 8B alignment)
            const u64 v = *(const u64*)&stS[rbase + rr][cp * 2];
#pragma unroll
            for (int o = 0; o < 2; o++) {
                const int j = rr - o;
                if (j >= 0 && j <= 10) acc[o] = ffma2(v, w2[j], acc[o]);
            }
        }
        const int obase = base + (h0 + rbase) * DVOL + w0 + cp * 2;
#pragma unroll
        for (int o = 0; o < 2; o++) {
            const float2 f = unpack2(acc[o]);
            // two adjacent half outputs -> one 32-bit store (idx is even)
            *(__half2*)(g4 + obase + o * DVOL) = __floats2half2_rn(f.x, f.y);
        }
    }
}

// ---------------------------------------------------------------------------
// Kernel 2: blur along D, ONE column per thread, 12-slot rings with PAIRED
// D-steps: each pair issues 6 LDGs together, then two full convolutions
// (double MLP, no extra prefetch registers). grid: (200, 8).
// ---------------------------------------------------------------------------
__global__ __launch_bounds__(256) void k_blur_d_ssim()
{
    __half2 gw2[11];
    {
        const float GW[11] = GW_INIT;
#pragma unroll
        for (int j = 0; j < 11; j++) gw2[j] = __float2half2_rn(GW[j]);
    }

    const int col = blockIdx.x * 256 + threadIdx.x;   // 0..51199
    const int n  = col / HWS;
    const int hw = col - n * HWS;
    const int dstart = blockIdx.y * DSEG;
    const int base = n * VOL + hw;

    const __half2 hz = __float2half2_rn(0.f);
    // 12-slot rings; slot of depth dep = (dep - dstart + 5) % 12 (compile-time
    // under full unroll).
    __half2 r01[12], r23[12];
    float r4[12];
#pragma unroll
    for (int k = 0; k < 12; k++) { r01[k] = hz; r23[k] = hz; r4[k] = 0.f; }

    // preload rel 0..9 (depths dstart-5 .. dstart+4) into slots 0..9
#pragma unroll
    for (int k = 0; k < 10; k++) {
        const int dep = dstart - 5 + k;
        if (dep >= 0) {
            const int idx = base + dep * HWS;
            r01[k] = g01[idx];
            r23[k] = g23[idx];
            r4[k]  = __half2float(g4[idx]);
        }
    }

    float ssim_acc = 0.f;
    const float GW[11] = GW_INIT;

#pragma unroll
    for (int p = 0; p < DSEG / 2; p++) {
        const int s0 = 2 * p;
        // --- load the two entries this pair needs (rel s0+10, s0+11) ------
#pragma unroll
        for (int e = 0; e < 2; e++) {
            const int sl = (s0 + 10 + e) % 12;        // compile-time
            const int dep = dstart + s0 + 5 + e;
            if (dep < DVOL) {
                const int idx = base + dep * HWS;
                r01[sl] = g01[idx];
                r23[sl] = g23[idx];
                r4[sl]  = __half2float(g4[idx]);
            } else {
                r01[sl] = hz; r23[sl] = hz; r4[sl] = 0.f;
            }
        }
        // --- two convolutions + SSIM --------------------------------------
#pragma unroll
        for (int e = 0; e < 2; e++) {
            const int s = s0 + e;
            __half2 m = hz, ev2 = hz;
            float e12 = 0.f;
#pragma unroll
            for (int j = 0; j < 11; j++) {
                const int q = (s + j) % 12;           // compile-time
                m   = __hfma2(gw2[j], r01[q], m);
                ev2 = __hfma2(gw2[j], r23[q], ev2);
                e12 += GW[j] * r4[q];
            }
            const float2 mu = __half22float2(m);
            const float2 ev = __half22float2(ev2);
            const float mu1sq = mu.x * mu.x;
            const float mu2sq = mu.y * mu.y;
            const float mu12  = mu.x * mu.y;
            const float s1  = ev.x - mu1sq;
            const float s2  = ev.y - mu2sq;
            const float s12 = e12 - mu12;
            const float C1 = 1e-4f, C2 = 9e-4f;
            const float num = (2.f * mu12 + C1) * (2.f * s12 + C2);
            const float den = (mu1sq + mu2sq + C1) * (s1 + s2 + C2) + 1e-12f;
            ssim_acc += __fdividef(num, den);
        }
    }

    // block reduction
    __shared__ float red[8];
#pragma unroll
    for (int o = 16; o; o >>= 1)
        ssim_acc += __shfl_down_sync(0xffffffffu, ssim_acc, o);
    if ((threadIdx.x & 31) == 0) red[threadIdx.x >> 5] = ssim_acc;
    __syncthreads();
    if (threadIdx.x == 0) {
        float s = 0.f;
#pragma unroll
        for (int k = 0; k < 8; k++) s += red[k];
        g_ssim_part[blockIdx.x + 200 * blockIdx.y] = s;
    }
}

// ---------------------------------------------------------------------------
// Final: reduce the partial arrays (8000 + 1600 floats) and combine.
// ---------------------------------------------------------------------------
__global__ __launch_bounds__(256) void k_final(float* __restrict__ out) {
    const int tid = threadIdx.x;
    double l1 = 0.0, ss = 0.0;
    for (int i = tid; i < K1_BLOCKS; i += 256) l1 += (double)g_l1_part[i];
    for (int i = tid; i < K2_BLOCKS; i += 256) ss += (double)g_ssim_part[i];

    __shared__ double rl[8], rs[8];
#pragma unroll
    for (int o = 16; o; o >>= 1) {
        l1 += __shfl_down_sync(0xffffffffu, l1, o);
        ss += __shfl_down_sync(0xffffffffu, ss, o);
    }
    if ((tid & 31) == 0) { rl[tid >> 5] = l1; rs[tid >> 5] = ss; }
    __syncthreads();
    if (tid == 0) {
        double a = 0.0, b = 0.0;
#pragma unroll
        for (int k = 0; k < 8; k++) { a += rl[k]; b += rs[k]; }
        const double inv = 1.0 / (double)NTOT;
        out[0] = (float)(0.7 * (a * inv) + 0.3 * (1.0 - b * inv));
    }
}

extern "C" void kernel_launch(void* const* d_in, const int* in_sizes, int n_in,
                              void* d_out, int out_size)
{
    const float* pred = (const float*)d_in[0];
    const float* tgt  = (const float*)d_in[1];
    float* out = (float*)d_out;

    dim3 g1(5, 5, 2 * DVOL);          // w-tiles, h-tiles, n*d
    k_blur_wh<<<g1, 256>>>(pred, tgt);

    dim3 g2((2 * HWS) / 256, 8);      // 200 x 8
    k_blur_d_ssim<<<g2, 256>>>();

    k_final<<<1, 256>>>(out);
}

// round 13
// speedup vs baseline: 2.1036x; 1.1403x over previous
#include <cuda_runtime.h>
#include <cuda_fp16.h>

// Problem constants
#define DVOL 160
#define HWS  25600            // 160*160
#define VOL  4096000          // 160^3
#define NTOT 8192000          // 2 * 160^3

#define K1_BLOCKS 8000        // 5*5*320
#define K2_BLOCKS 1600        // 200*8
#define DSEG 20               // depth segment length in k2

// Packed fp16 intermediates:
//   g01[idx] = half2(blur(p),   blur(t))
//   g23[idx] = half2(blur(p*p), blur(t*t))
//   g4 [idx] = half (blur(p*t))
__device__ __half2 g01[NTOT];
__device__ __half2 g23[NTOT];
__device__ __half  g4[NTOT];
__device__ float g_l1_part[K1_BLOCKS];
__device__ float g_ssim_part[K2_BLOCKS];
__device__ unsigned g_done;          // completion counter (reset each run)

// Gaussian weights (size 11, sigma 1.5, normalized).
#define GW_INIT {0.00102838f, 0.00759876f, 0.03600078f, 0.10936070f, \
                 0.21300554f, 0.26601172f, 0.21300554f, 0.10936070f, \
                 0.03600078f, 0.00759876f, 0.00102838f}

// ---- packed f32x2 helpers (Blackwell FFMA2 path, PTX-only) ---------------
typedef unsigned long long u64;

__device__ __forceinline__ u64 ffma2(u64 a, u64 b, u64 c) {
    u64 r;
    asm("fma.rn.f32x2 %0, %1, %2, %3;" : "=l"(r) : "l"(a), "l"(b), "l"(c));
    return r;
}
__device__ __forceinline__ u64 fmul2(u64 a, u64 b) {
    u64 r;
    asm("mul.rn.f32x2 %0, %1, %2;" : "=l"(r) : "l"(a), "l"(b));
    return r;
}
__device__ __forceinline__ u64 pack2(float lo, float hi) {
    u64 r;
    asm("mov.b64 %0, {%1, %2};"
        : "=l"(r) : "r"(__float_as_uint(lo)), "r"(__float_as_uint(hi)));
    return r;
}
__device__ __forceinline__ float2 unpack2(u64 v) {
    unsigned lo, hi;
    asm("mov.b64 {%0, %1}, %2;" : "=r"(lo), "=r"(hi) : "l"(v));
    return make_float2(__uint_as_float(lo), __uint_as_float(hi));
}

// ---------------------------------------------------------------------------
// Kernel 1: per (n,d) slice, fused W-blur + H-blur of the 5 product channels,
// 32x32 tiles, f32x2 math, packed fp16 out + L1 partial.
// NOTE: no min-blocks launch bound — phase A needs its 62 registers.
// ---------------------------------------------------------------------------
__global__ __launch_bounds__(256) void k_blur_wh(
    const float* __restrict__ pred, const float* __restrict__ tgt)
{
    __shared__ u64 rpt[42][45];           // raw (p,t) packed; 8B-stride 45 mod 16 = 13
    __shared__ u64 stP[2][42][33];        // W-blurred pairs (p,t), (pp,tt)
    __shared__ float stS[42][34];         // W-blurred pt (pitch 34: LDS.64 aligned)
    __shared__ float red[8];

    const float GW[11] = GW_INIT;
    u64 w2[11];
#pragma unroll
    for (int j = 0; j < 11; j++) w2[j] = pack2(GW[j], GW[j]);

    const int bz = blockIdx.z;            // n*160 + d
    const int n  = bz / DVOL;
    const int d  = bz % DVOL;
    const int h0 = blockIdx.y * 32;
    const int w0 = blockIdx.x * 32;
    const int base = n * VOL + d * HWS;
    const int tid = threadIdx.x;

    // --- load raw 42x42 halo region via aligned float2 pairs ---------------
    // columns w0-6 .. w0+37 as 22 even-aligned float2 loads per row; pair
    // validity is all-or-nothing (gwe even): valid iff 0 <= gwe <= 158.
    for (int ii = tid; ii < 42 * 22; ii += 256) {
        const int r = ii / 22;
        const int i = ii - r * 22;
        const int gh = h0 - 5 + r;
        const int gwe = w0 - 6 + 2 * i;
        float2 p2 = make_float2(0.f, 0.f);
        float2 t2 = make_float2(0.f, 0.f);
        if ((unsigned)gh < 160u && (unsigned)gwe <= 158u) {
            const int idx = base + gh * DVOL + gwe;
            p2 = *(const float2*)(pred + idx);
            t2 = *(const float2*)(tgt + idx);
        }
        const int h = 2 * i - 1;              // logical halo col of the .x lane
        if (h >= 0)     rpt[r][h]     = pack2(p2.x, t2.x);
        if (h + 1 < 42) rpt[r][h + 1] = pack2(p2.y, t2.y);
    }
    __syncthreads();

    // --- L1 partial over the 32x32 interior -------------------------------
    float l1 = 0.f;
#pragma unroll
    for (int k = 0; k < 4; k++) {
        const int i = tid + (k << 8);
        const int hh = i >> 5, ww = i & 31;
        const float2 v = unpack2(rpt[5 + hh][5 + ww]);
        l1 += fabsf(v.x - v.y);
    }

    // --- phase A: blur along W, packed rings -------------------------------
    // thread = (row r in 0..41, col-group g in 0..5), each group covers 6 cols
    if (tid < 252) {
        const int g = tid / 42;
        const int r = tid - 42 * g;
        const int c0 = g * 6;

        u64 q01[11];
        float q4[11];
#pragma unroll
        for (int k = 0; k < 10; k++) {
            const u64 v = rpt[r][c0 + k];
            q01[k] = v;
            const float2 f = unpack2(v);
            q4[k] = f.x * f.y;
        }
#pragma unroll
        for (int s = 0; s < 6; s++) {
            const int c = c0 + s;
            if (c < 32) {
                const u64 v = rpt[r][c + 10];
                const int sl = (s + 10) % 11;
                q01[sl] = v;
                {
                    const float2 f = unpack2(v);
                    q4[sl] = f.x * f.y;
                }
                u64 a01 = 0ull, a23 = 0ull;
                float a4 = 0.f;
#pragma unroll
                for (int j = 0; j < 11; j++) {
                    const int q = (s + j) % 11;
                    const u64 x = q01[q];
                    a01 = ffma2(x, w2[j], a01);
                    a23 = ffma2(fmul2(x, x), w2[j], a23);
                    a4 += GW[j] * q4[q];
                }
                stP[0][r][c] = a01;
                stP[1][r][c] = a23;
                stS[r][c] = a4;
            }
        }
    }

    // reduce L1 (warp shuffles, then smem) — overlaps with phase A compute
#pragma unroll
    for (int o = 16; o; o >>= 1) l1 += __shfl_down_sync(0xffffffffu, l1, o);
    if ((tid & 31) == 0) red[tid >> 5] = l1;

    __syncthreads();   // stP/stS ready + red ready

    if (tid == 0) {
        float s = 0.f;
#pragma unroll
        for (int k = 0; k < 8; k++) s += red[k];
        const int bidlin = blockIdx.x + 5 * (blockIdx.y + 5 * blockIdx.z);
        g_l1_part[bidlin] = s;
    }

    // --- phase B pass 1: packed pairs on ALL 256 threads -------------------
    // thread = (channel ch in 0..1, hgroup hg in 0..3 of 8 rows, col ww)
    {
        const int ch  = tid >> 7;            // 0 or 1
        const int sub = tid & 127;
        const int hg  = sub >> 5;            // 0..3
        const int ww  = sub & 31;
        const int rbase = hg * 8;

        u64 acc[8];
#pragma unroll
        for (int o = 0; o < 8; o++) acc[o] = 0ull;
#pragma unroll
        for (int rr = 0; rr < 18; rr++) {
            const u64 v = stP[ch][rbase + rr][ww];
#pragma unroll
            for (int o = 0; o < 8; o++) {
                const int j = rr - o;                 // compile-time bounds
                if (j >= 0 && j <= 10) acc[o] = ffma2(v, w2[j], acc[o]);
            }
        }
        __half2* __restrict__ out = ch ? g23 : g01;
        const int obase = base + (h0 + rbase) * DVOL + w0 + ww;
#pragma unroll
        for (int o = 0; o < 8; o++) {
            const float2 f = unpack2(acc[o]);
            out[obase + o * DVOL] = __floats2half2_rn(f.x, f.y);
        }
    }

    // --- phase B pass 2: pt channel, column-paired f32x2 on 256 threads ----
    // thread = (hgroup hg in 0..15 of 2 rows, colpair cp in 0..15)
    {
        const int hg = tid >> 4;             // 0..15
        const int cp = tid & 15;             // 0..15
        const int rbase = hg * 2;

        u64 acc[2];
        acc[0] = 0ull; acc[1] = 0ull;
#pragma unroll
        for (int rr = 0; rr < 12; rr++) {
            // LDS.64 of two adjacent columns (pitch 34 keeps 8B alignment)
            const u64 v = *(const u64*)&stS[rbase + rr][cp * 2];
#pragma unroll
            for (int o = 0; o < 2; o++) {
                const int j = rr - o;
                if (j >= 0 && j <= 10) acc[o] = ffma2(v, w2[j], acc[o]);
            }
        }
        const int obase = base + (h0 + rbase) * DVOL + w0 + cp * 2;
#pragma unroll
        for (int o = 0; o < 2; o++) {
            const float2 f = unpack2(acc[o]);
            // two adjacent half outputs -> one 32-bit store (idx is even)
            *(__half2*)(g4 + obase + o * DVOL) = __floats2half2_rn(f.x, f.y);
        }
    }
}

// ---------------------------------------------------------------------------
// Kernel 2: blur along D, ONE column per thread, 12-slot rings with PAIRED
// D-steps (each pair issues 6 LDGs, then two full convolutions). The LAST
// block to finish also performs the final reduction (folds k_final).
// grid: (200, 8).
// ---------------------------------------------------------------------------
__global__ __launch_bounds__(256) void k_blur_d_ssim(float* __restrict__ out)
{
    __half2 gw2[11];
    {
        const float GW[11] = GW_INIT;
#pragma unroll
        for (int j = 0; j < 11; j++) gw2[j] = __float2half2_rn(GW[j]);
    }

    const int col = blockIdx.x * 256 + threadIdx.x;   // 0..51199
    const int n  = col / HWS;
    const int hw = col - n * HWS;
    const int dstart = blockIdx.y * DSEG;
    const int base = n * VOL + hw;

    const __half2 hz = __float2half2_rn(0.f);
    // 12-slot rings; all slot indices compile-time under full unroll.
    __half2 r01[12], r23[12];
    float r4[12];
#pragma unroll
    for (int k = 0; k < 12; k++) { r01[k] = hz; r23[k] = hz; r4[k] = 0.f; }

    // preload rel 0..9 (depths dstart-5 .. dstart+4) into slots 0..9
#pragma unroll
    for (int k = 0; k < 10; k++) {
        const int dep = dstart - 5 + k;
        if (dep >= 0) {
            const int idx = base + dep * HWS;
            r01[k] = g01[idx];
            r23[k] = g23[idx];
            r4[k]  = __half2float(g4[idx]);
        }
    }

    float ssim_acc = 0.f;
    const float GW[11] = GW_INIT;

#pragma unroll
    for (int p = 0; p < DSEG / 2; p++) {
        const int s0 = 2 * p;
        // --- load the two entries this pair needs (rel s0+10, s0+11) ------
#pragma unroll
        for (int e = 0; e < 2; e++) {
            const int sl = (s0 + 10 + e) % 12;        // compile-time
            const int dep = dstart + s0 + 5 + e;
            if (dep < DVOL) {
                const int idx = base + dep * HWS;
                r01[sl] = g01[idx];
                r23[sl] = g23[idx];
                r4[sl]  = __half2float(g4[idx]);
            } else {
                r01[sl] = hz; r23[sl] = hz; r4[sl] = 0.f;
            }
        }
        // --- two convolutions + SSIM --------------------------------------
#pragma unroll
        for (int e = 0; e < 2; e++) {
            const int s = s0 + e;
            __half2 m = hz, ev2 = hz;
            float e12 = 0.f;
#pragma unroll
            for (int j = 0; j < 11; j++) {
                const int q = (s + j) % 12;           // compile-time
                m   = __hfma2(gw2[j], r01[q], m);
                ev2 = __hfma2(gw2[j], r23[q], ev2);
                e12 += GW[j] * r4[q];
            }
            const float2 mu = __half22float2(m);
            const float2 ev = __half22float2(ev2);
            const float mu1sq = mu.x * mu.x;
            const float mu2sq = mu.y * mu.y;
            const float mu12  = mu.x * mu.y;
            const float s1  = ev.x - mu1sq;
            const float s2  = ev.y - mu2sq;
            const float s12 = e12 - mu12;
            const float C1 = 1e-4f, C2 = 9e-4f;
            const float num = (2.f * mu12 + C1) * (2.f * s12 + C2);
            const float den = (mu1sq + mu2sq + C1) * (s1 + s2 + C2) + 1e-12f;
            ssim_acc += __fdividef(num, den);
        }
    }

    // block reduction
    __shared__ float red[8];
    __shared__ int last;
#pragma unroll
    for (int o = 16; o; o >>= 1)
        ssim_acc += __shfl_down_sync(0xffffffffu, ssim_acc, o);
    if ((threadIdx.x & 31) == 0) red[threadIdx.x >> 5] = ssim_acc;
    __syncthreads();
    if (threadIdx.x == 0) {
        float s = 0.f;
#pragma unroll
        for (int k = 0; k < 8; k++) s += red[k];
        g_ssim_part[blockIdx.x + 200 * blockIdx.y] = s;
        __threadfence();
        last = (atomicAdd(&g_done, 1u) == K2_BLOCKS - 1) ? 1 : 0;
    }
    __syncthreads();

    // --- last block folds the final reduction (replaces k_final) ----------
    if (last) {
        const int tid = threadIdx.x;
        float l1 = 0.f, ss = 0.f;
        for (int i = tid; i < K1_BLOCKS; i += 256) l1 += g_l1_part[i];
        for (int i = tid; i < K2_BLOCKS; i += 256) ss += g_ssim_part[i];
#pragma unroll
        for (int o = 16; o; o >>= 1) {
            l1 += __shfl_down_sync(0xffffffffu, l1, o);
            ss += __shfl_down_sync(0xffffffffu, ss, o);
        }
        __shared__ float rl[8], rs[8];
        if ((tid & 31) == 0) { rl[tid >> 5] = l1; rs[tid >> 5] = ss; }
        __syncthreads();
        if (tid == 0) {
            float a = 0.f, b = 0.f;
#pragma unroll
            for (int k = 0; k < 8; k++) { a += rl[k]; b += rs[k]; }
            const float inv = 1.0f / (float)NTOT;
            out[0] = 0.7f * (a * inv) + 0.3f * (1.0f - b * inv);
            g_done = 0;                      // reset for next graph replay
        }
    }
}

extern "C" void kernel_launch(void* const* d_in, const int* in_sizes, int n_in,
                              void* d_out, int out_size)
{
    const float* pred = (const float*)d_in[0];
    const float* tgt  = (const float*)d_in[1];
    float* out = (float*)d_out;

    dim3 g1(5, 5, 2 * DVOL);          // w-tiles, h-tiles, n*d
    k_blur_wh<<<g1, 256>>>(pred, tgt);

    dim3 g2((2 * HWS) / 256, 8);      // 200 x 8
    k_blur_d_ssim<<<g2, 256>>>(out);
}